// round 14
// baseline (speedup 1.0000x reference)
#include <cuda_runtime.h>
#include <math_constants.h>

// ---------------------------------------------------------------------------
// MultiSegmentLoss fused kernel — single launch, single wave (2 blocks/SM),
// x4 elements per thread, register double-buffered loads, QUAD-phased
// processing (R9 structure), O(1) LUT match (right endpoint fused in seg.w),
// GIoU==IoU identity, a2 via cl-reuse, merged uni*hw reciprocal.
// ---------------------------------------------------------------------------

#define MAXPART 8192
#define LUTSIZE 4096                    // bins over [0,256) -> width 1/16

__device__ float        g_part[MAXPART * 8];
__device__ unsigned int g_count = 0;

struct Accum { float a0, a1, a2, a3, a4, a5, a6; };

__device__ __forceinline__ void epilogue_elem(
    float c256, const float4 sg, float pl, float pr, float cdx, float cdy,
    float pldx, float pldy, float pcdx, float pcdy, float lg, Accum& A)
{
    const float EPS = 1.1920929e-7f;   // jnp.finfo(float32).eps

    const bool pos = (sg.z > 0.0f);
    float ltl = c256 - sg.x;
    float ltr = sg.y - c256;

    float inter = fminf(pl, ltl) + fminf(pr, ltr);
    float uni   = pl + pr + ltl + ltr - inter;   // == max+max >= pl+pr >= 2
    const bool ppos = pos && (inter >= 0.5f * uni);   // iou >= 0.5
    float posf = pos  ? 1.0f : 0.0f;
    float ppf  = ppos ? 1.0f : 0.0f;

    float hw = 0.5f * (pl + pr);
    // merged reciprocal: one MUFU for both 1/uni and 1/hw
    float r   = __fdividef(1.0f, uni * hw);
    float iou = inter * hw * r;
    float rhw = uni * r;

    // 1-D identity: enclosing interval == union, so giou == iou.
    A.a0 += (1.0f - iou) * posf;

    float cl0 = hw * pldx + pl;
    float cl1 = hw * pldy + pr;

    // prop-loc L1: pldx-(ltl-pl)/hw == (cl0-ltl)*rhw
    A.a2 += (fabsf(cl0 - ltl) + fabsf(cl1 - ltr)) * rhw * ppf;

    // centerness BCE vs clipped iou of refined location
    float in2  = fminf(cl0, ltl) + fminf(cl1, ltr);
    float un2  = cl0 + cl1 + ltl + ltr - in2;
    float iou2 = fmaxf(__fdividef(in2, fmaxf(un2, EPS)), 0.0f);
    float bce  = fmaxf(lg, 0.0f) - lg * iou2 + __logf(1.0f + __expf(-fabsf(lg)));
    A.a4 += bce * posf;

    // focal(conf): pt = sigmoid(target - other) (+eps)
    {
        float dd = cdx - cdy;
        float d  = pos ? dd : -dd;
        float pt = __fdividef(1.0f, 1.0f + __expf(d)) + 1e-6f;
        float al = pos ? 0.75f : 0.25f;
        float om = 1.0f - pt;
        A.a1 -= om * om * al * __logf(pt);
    }
    // focal(prop_conf)
    {
        float dd = pcdx - pcdy;
        float d  = ppos ? dd : -dd;
        float pt = __fdividef(1.0f, 1.0f + __expf(d)) + 1e-6f;
        float al = ppos ? 0.75f : 0.25f;
        float om = 1.0f - pt;
        A.a3 -= om * om * al * __logf(pt);
    }
    A.a5 += posf;
    A.a6 += ppf;
}

struct QuadBuf { float4 v[10]; };   // pc, lg, pre0, pre1, pld0, pld1, cd0, cd1, pcd0, pcd1

__device__ __forceinline__ void load_quad(
    int q,
    const float4* __restrict__ pri4, const float4* __restrict__ ctr4,
    const float4* __restrict__ loc4, const float4* __restrict__ pld4,
    const float4* __restrict__ cd4,  const float4* __restrict__ pcd4,
    QuadBuf& B)
{
    B.v[0] = pri4[q];                    // priors reused across batches -> cache
    B.v[1] = __ldcs(ctr4 + q);
    B.v[2] = __ldcs(loc4 + 2 * q);
    B.v[3] = __ldcs(loc4 + 2 * q + 1);
    B.v[4] = __ldcs(pld4 + 2 * q);
    B.v[5] = __ldcs(pld4 + 2 * q + 1);
    B.v[6] = __ldcs(cd4  + 2 * q);
    B.v[7] = __ldcs(cd4  + 2 * q + 1);
    B.v[8] = __ldcs(pcd4 + 2 * q);
    B.v[9] = __ldcs(pcd4 + 2 * q + 1);
}

__device__ __forceinline__ void process_quad(
    const QuadBuf& B, const float4* __restrict__ seg,
    const unsigned short* __restrict__ lut, Accum& A)
{
    // ---- phase 1: batched matches (4 overlapping LDS chains) ----
    // bin index from the raw prior (off the critical path of c = px*256)
    int bin[4] = { (int)(B.v[0].x * (float)LUTSIZE),
                   (int)(B.v[0].y * (float)LUTSIZE),
                   (int)(B.v[0].z * (float)LUTSIZE),
                   (int)(B.v[0].w * (float)LUTSIZE) };
    float c[4] = { B.v[0].x * 256.0f, B.v[0].y * 256.0f,
                   B.v[0].z * 256.0f, B.v[0].w * 256.0f };
    int si[4];
    #pragma unroll
    for (int i = 0; i < 4; i++)
        si[i] = lut[bin[i]];
    float4 sg[4];
    #pragma unroll
    for (int i = 0; i < 4; i++)
        sg[i] = seg[si[i]];
    #pragma unroll
    for (int i = 0; i < 4; i++)
        while (sg[i].w < c[i]) { si[i]++; sg[i] = seg[si[i]]; }   // rare, bounded

    // ---- phase 2: 4 independent epilogue chains, operands all ready ----
    epilogue_elem(c[0], sg[0], B.v[2].x, B.v[2].y, B.v[6].x, B.v[6].y,
                  B.v[4].x, B.v[4].y, B.v[8].x, B.v[8].y, B.v[1].x, A);
    epilogue_elem(c[1], sg[1], B.v[2].z, B.v[2].w, B.v[6].z, B.v[6].w,
                  B.v[4].z, B.v[4].w, B.v[8].z, B.v[8].w, B.v[1].y, A);
    epilogue_elem(c[2], sg[2], B.v[3].x, B.v[3].y, B.v[7].x, B.v[7].y,
                  B.v[5].x, B.v[5].y, B.v[9].x, B.v[9].y, B.v[1].z, A);
    epilogue_elem(c[3], sg[3], B.v[3].z, B.v[3].w, B.v[7].z, B.v[7].w,
                  B.v[5].z, B.v[5].w, B.v[9].z, B.v[9].w, B.v[1].w, A);
}

__global__ __launch_bounds__(256, 2) void msl_main(
    const float* __restrict__ loc,
    const float* __restrict__ conf_d,
    const float* __restrict__ ploc,
    const float* __restrict__ pconf_d,
    const float* __restrict__ center,
    const float* __restrict__ priors,
    const float* __restrict__ targets,
    int K, int N, int nblk,
    float* __restrict__ out, int out_size)
{
    extern __shared__ float sh[];
    const int M = 2 * N;
    float4* seg    = reinterpret_cast<float4*>(sh);               // M+1
    float2* sp     = reinterpret_cast<float2*>(seg + (M + 1));    // N
    float2* raw    = sp + N;                                      // N
    float*  slab   = reinterpret_cast<float*>(raw + N);           // N
    float*  rawlab = slab + N;                                    // N
    float*  ebp    = rawlab + N;                                  // M+1 (INF pad)
    unsigned short* lut = reinterpret_cast<unsigned short*>(ebp + (M + 1));

    const int b = blockIdx.y;
    const float* tg = targets + (size_t)b * N * 3;

    if (threadIdx.x < N) {
        int i = threadIdx.x;
        raw[i]    = make_float2(tg[i * 3 + 0] * 256.0f, tg[i * 3 + 1] * 256.0f);
        rawlab[i] = tg[i * 3 + 2];
    }
    __syncthreads();
    if (threadIdx.x < N) {                          // stable width rank-sort
        int i = threadIdx.x;
        float2 ti = raw[i];
        float  wi = ti.y - ti.x;
        int rank = 0;
        for (int j = 0; j < N; j++) {
            float2 tj = raw[j];
            float  wj = tj.y - tj.x;
            rank += (wj < wi) || (wj == wi && j < i);
        }
        sp[rank]   = ti;
        slab[rank] = rawlab[i];
    }
    if (threadIdx.x < M) {                          // stable endpoint rank-sort
        int i = threadIdx.x;
        float vi = (i < N) ? raw[i].x : raw[i - N].y;
        int rank = 0;
        for (int j = 0; j < M; j++) {
            float vj = (j < N) ? raw[j].x : raw[j - N].y;
            rank += (vj < vi) || (vj == vi && j < i);
        }
        ebp[rank] = vi;
    }
    if (threadIdx.x == M) ebp[M] = CUDART_INF_F;
    __syncthreads();
    for (int s = threadIdx.x; s <= M; s += blockDim.x) {   // segment table
        float rep;
        if (s == 0)      rep = ebp[0] - 1.0f;
        else if (s == M) rep = ebp[M - 1] + 1.0f;
        else             rep = 0.5f * (ebp[s - 1] + ebp[s]);
        float t0 = 0.f, t1 = 0.f, lb = 0.f;
        for (int n = 0; n < N; n++) {
            float2 t = sp[n];
            if (rep >= t.x && rep <= t.y) { t0 = t.x; t1 = t.y; lb = slab[n]; break; }
        }
        seg[s] = make_float4(t0, t1, lb, ebp[s]);
    }
    for (int bin = threadIdx.x; bin < LUTSIZE; bin += blockDim.x) {
        float edge = (float)bin * (256.0f / LUTSIZE);
        int s = 0;
        #pragma unroll
        for (int step = 64; step >= 1; step >>= 1) {
            int ns = s + step;
            if (ns <= M && ebp[ns - 1] < edge) s = ns;
        }
        lut[bin] = (unsigned short)s;
    }
    __syncthreads();

    Accum A = {0.f, 0.f, 0.f, 0.f, 0.f, 0.f, 0.f};
    const int Kq = K >> 2;                          // quads
    const size_t baseq = (size_t)b * (size_t)Kq;

    const float4* loc4  = reinterpret_cast<const float4*>(loc)     + 2 * baseq;
    const float4* cd4   = reinterpret_cast<const float4*>(conf_d)  + 2 * baseq;
    const float4* pld4  = reinterpret_cast<const float4*>(ploc)    + 2 * baseq;
    const float4* pcd4  = reinterpret_cast<const float4*>(pconf_d) + 2 * baseq;
    const float4* ctr4  = reinterpret_cast<const float4*>(center)  + baseq;
    const float4* pri4  = reinterpret_cast<const float4*>(priors);

    const int stride = gridDim.x * blockDim.x;

    // ---- software-pipelined main loop (register double buffer) ----
    QuadBuf bufA, bufB;
    int p = blockIdx.x * blockDim.x + threadIdx.x;
    bool valid = (p < Kq);
    if (valid) load_quad(p, pri4, ctr4, loc4, pld4, cd4, pcd4, bufA);
    while (valid) {
        int  pn = p + stride;
        bool vn = (pn < Kq);
        if (vn) load_quad(pn, pri4, ctr4, loc4, pld4, cd4, pcd4, bufB);
        process_quad(bufA, seg, lut, A);
        p = pn; valid = vn;
        if (!valid) break;
        pn = p + stride;
        vn = (pn < Kq);
        if (vn) load_quad(pn, pri4, ctr4, loc4, pld4, cd4, pcd4, bufA);
        process_quad(bufB, seg, lut, A);
        p = pn; valid = vn;
    }

    // K % 4 tail (not hit for K=200000; kept for generality)
    if ((K & 3) && blockIdx.x == 0 && threadIdx.x == 0) {
        const size_t base = (size_t)b * (size_t)K;
        for (int k = Kq * 4; k < K; k++) {
            float c = priors[k] * 256.0f;
            int s = lut[(int)(priors[k] * (float)LUTSIZE)];
            float4 sgk = seg[s];
            while (sgk.w < c) { s++; sgk = seg[s]; }
            float2 pre = reinterpret_cast<const float2*>(loc)[base + k];
            float2 pld = reinterpret_cast<const float2*>(ploc)[base + k];
            float2 cd  = reinterpret_cast<const float2*>(conf_d)[base + k];
            float2 pcd = reinterpret_cast<const float2*>(pconf_d)[base + k];
            epilogue_elem(c, sgk, pre.x, pre.y, cd.x, cd.y,
                          pld.x, pld.y, pcd.x, pcd.y, center[base + k], A);
        }
    }

    // warp reduction
    #pragma unroll
    for (int off = 16; off; off >>= 1) {
        A.a0 += __shfl_down_sync(0xffffffffu, A.a0, off);
        A.a1 += __shfl_down_sync(0xffffffffu, A.a1, off);
        A.a2 += __shfl_down_sync(0xffffffffu, A.a2, off);
        A.a3 += __shfl_down_sync(0xffffffffu, A.a3, off);
        A.a4 += __shfl_down_sync(0xffffffffu, A.a4, off);
        A.a5 += __shfl_down_sync(0xffffffffu, A.a5, off);
        A.a6 += __shfl_down_sync(0xffffffffu, A.a6, off);
    }
    __shared__ float red[8][8];
    int w  = threadIdx.x >> 5;
    int ln = threadIdx.x & 31;
    if (ln == 0) {
        red[w][0] = A.a0; red[w][1] = A.a1; red[w][2] = A.a2; red[w][3] = A.a3;
        red[w][4] = A.a4; red[w][5] = A.a5; red[w][6] = A.a6;
    }
    __syncthreads();
    const int blk = blockIdx.y * gridDim.x + blockIdx.x;
    if (threadIdx.x < 7) {
        float v = 0.0f;
        #pragma unroll
        for (int i = 0; i < 8; i++) v += red[i][threadIdx.x];
        g_part[blk * 8 + threadIdx.x] = v;   // deterministic per-block slot
    }
    __syncthreads();

    // ---- last-block finalize (deterministic fixed-order sum) ----
    __shared__ unsigned int s_ticket;
    if (threadIdx.x == 0) {
        __threadfence();
        s_ticket = atomicAdd(&g_count, 1u);
    }
    __syncthreads();
    if (s_ticket == (unsigned)(nblk - 1)) {
        __threadfence();
        __shared__ float tot[7];
        if (w < 7) {
            float v = 0.0f;
            for (int i = ln; i < nblk; i += 32) v += g_part[i * 8 + w];
            #pragma unroll
            for (int off = 16; off; off >>= 1) v += __shfl_down_sync(0xffffffffu, v, off);
            if (ln == 0) tot[w] = v;
        }
        __syncthreads();
        if (threadIdx.x == 0) {
            g_count = 0;                       // self-reset for graph replay
            float np = fmaxf(tot[5], 1.0f);
            float pn = fmaxf(tot[6], 1.0f);
            if (out_size > 0) out[0] = tot[0] / np;   // loss_l / Np
            if (out_size > 1) out[1] = tot[1] / np;   // loss_c / Np
            if (out_size > 2) out[2] = tot[2] / pn;   // loss_prop_l / PN
            if (out_size > 3) out[3] = tot[3] / pn;   // loss_prop_c / PN
            if (out_size > 4) out[4] = tot[4] / np;   // loss_ct / Np
        }
    }
}

extern "C" void kernel_launch(void* const* d_in, const int* in_sizes, int n_in,
                              void* d_out, int out_size)
{
    const float* loc     = (const float*)d_in[0];
    const float* conf    = (const float*)d_in[1];
    const float* ploc    = (const float*)d_in[2];
    const float* pconf   = (const float*)d_in[3];
    const float* center  = (const float*)d_in[4];
    const float* priors  = (const float*)d_in[5];
    const float* targets = (const float*)d_in[6];

    int K = in_sizes[5];                 // priors: (K,1)
    int B = in_sizes[4] / K;             // center: (B,K,1)
    int N = in_sizes[6] / (B * 3);       // targets: (B,N,3)
    int M = 2 * N;

    // Single wave at 2 blocks/SM: 2 * 148 = 296 slots.
    int gx = 296 / (B > 0 ? B : 1);
    if (gx < 1) gx = 1;
    while ((long)gx * B > MAXPART && gx > 1) gx /= 2;
    int nblk = gx * B;

    dim3 grid(gx, B);
    size_t shmem = (size_t)(M + 1) * 16        // seg float4
                 + (size_t)N * 8 * 2           // sp + raw float2
                 + (size_t)N * 4 * 2           // slab + rawlab
                 + (size_t)(M + 1) * 4         // ebp (+sentinel)
                 + (size_t)LUTSIZE * 2;        // u16 lut
    msl_main<<<grid, 256, shmem>>>(loc, conf, ploc, pconf, center, priors,
                                   targets, K, N, nblk, (float*)d_out, out_size);
}

// round 15
// speedup vs baseline: 1.0127x; 1.0127x over previous
#include <cuda_runtime.h>
#include <math_constants.h>

// ---------------------------------------------------------------------------
// MultiSegmentLoss fused kernel — single launch, single wave (3 blocks/SM),
// x2 elements per thread, register double-buffered loads, O(1) LUT match
// (right endpoint fused into seg.w), GIoU==IoU identity, a2 via cl-reuse,
// merged uni*hw reciprocal. More warps (24/SM) x prefetch.
// ---------------------------------------------------------------------------

#define MAXPART 8192
#define LUTSIZE 4096                    // bins over [0,256) -> width 1/16

__device__ float        g_part[MAXPART * 8];
__device__ unsigned int g_count = 0;

struct Accum { float a0, a1, a2, a3, a4, a5, a6; };

__device__ __forceinline__ void epilogue_elem(
    float c256, const float4 sg, float pl, float pr, float cdx, float cdy,
    float pldx, float pldy, float pcdx, float pcdy, float lg, Accum& A)
{
    const float EPS = 1.1920929e-7f;   // jnp.finfo(float32).eps

    const bool pos = (sg.z > 0.0f);
    float ltl = c256 - sg.x;
    float ltr = sg.y - c256;

    float inter = fminf(pl, ltl) + fminf(pr, ltr);
    float uni   = pl + pr + ltl + ltr - inter;   // == max+max >= pl+pr >= 2
    const bool ppos = pos && (inter >= 0.5f * uni);   // iou >= 0.5
    float posf = pos  ? 1.0f : 0.0f;
    float ppf  = ppos ? 1.0f : 0.0f;

    float hw = 0.5f * (pl + pr);
    // merged reciprocal: one MUFU for both 1/uni and 1/hw
    float r   = __fdividef(1.0f, uni * hw);
    float iou = inter * hw * r;
    float rhw = uni * r;

    // 1-D identity: enclosing interval == union, so giou == iou.
    A.a0 += (1.0f - iou) * posf;

    float cl0 = hw * pldx + pl;
    float cl1 = hw * pldy + pr;

    // prop-loc L1: pldx-(ltl-pl)/hw == (cl0-ltl)*rhw
    A.a2 += (fabsf(cl0 - ltl) + fabsf(cl1 - ltr)) * rhw * ppf;

    // centerness BCE vs clipped iou of refined location
    float in2  = fminf(cl0, ltl) + fminf(cl1, ltr);
    float un2  = cl0 + cl1 + ltl + ltr - in2;
    float iou2 = fmaxf(__fdividef(in2, fmaxf(un2, EPS)), 0.0f);
    float bce  = fmaxf(lg, 0.0f) - lg * iou2 + __logf(1.0f + __expf(-fabsf(lg)));
    A.a4 += bce * posf;

    // focal(conf): pt = sigmoid(target - other) (+eps)
    {
        float dd = cdx - cdy;
        float d  = pos ? dd : -dd;
        float pt = __fdividef(1.0f, 1.0f + __expf(d)) + 1e-6f;
        float al = pos ? 0.75f : 0.25f;
        float om = 1.0f - pt;
        A.a1 -= om * om * al * __logf(pt);
    }
    // focal(prop_conf)
    {
        float dd = pcdx - pcdy;
        float d  = ppos ? dd : -dd;
        float pt = __fdividef(1.0f, 1.0f + __expf(d)) + 1e-6f;
        float al = ppos ? 0.75f : 0.25f;
        float om = 1.0f - pt;
        A.a3 -= om * om * al * __logf(pt);
    }
    A.a5 += posf;
    A.a6 += ppf;
}

// per-pair register buffer: 20 floats
struct PairBuf {
    float4 pre, pld, cd, pcd;   // 2 elems each
    float2 pc, lg;
};

__device__ __forceinline__ void load_pair(
    int p,
    const float2* __restrict__ pri2, const float2* __restrict__ ctr2,
    const float4* __restrict__ loc4, const float4* __restrict__ pld4,
    const float4* __restrict__ cd4,  const float4* __restrict__ pcd4,
    PairBuf& B)
{
    B.pc  = pri2[p];                  // priors reused across batches -> cache
    B.lg  = __ldcs(ctr2 + p);
    B.pre = __ldcs(loc4 + p);
    B.pld = __ldcs(pld4 + p);
    B.cd  = __ldcs(cd4  + p);
    B.pcd = __ldcs(pcd4 + p);
}

__device__ __forceinline__ void process_pair(
    const PairBuf& B, const float4* __restrict__ seg,
    const unsigned short* __restrict__ lut, Accum& A)
{
    // batched matches (2 overlapping LDS chains)
    float c0 = B.pc.x * 256.0f;
    float c1 = B.pc.y * 256.0f;
    int s0 = lut[(int)(B.pc.x * (float)LUTSIZE)];
    int s1 = lut[(int)(B.pc.y * (float)LUTSIZE)];
    float4 sg0 = seg[s0];
    float4 sg1 = seg[s1];
    while (sg0.w < c0) { s0++; sg0 = seg[s0]; }   // rare, sentinel-bounded
    while (sg1.w < c1) { s1++; sg1 = seg[s1]; }

    epilogue_elem(c0, sg0, B.pre.x, B.pre.y, B.cd.x, B.cd.y,
                  B.pld.x, B.pld.y, B.pcd.x, B.pcd.y, B.lg.x, A);
    epilogue_elem(c1, sg1, B.pre.z, B.pre.w, B.cd.z, B.cd.w,
                  B.pld.z, B.pld.w, B.pcd.z, B.pcd.w, B.lg.y, A);
}

__global__ __launch_bounds__(256, 3) void msl_main(
    const float* __restrict__ loc,
    const float* __restrict__ conf_d,
    const float* __restrict__ ploc,
    const float* __restrict__ pconf_d,
    const float* __restrict__ center,
    const float* __restrict__ priors,
    const float* __restrict__ targets,
    int K, int N, int nblk,
    float* __restrict__ out, int out_size)
{
    extern __shared__ float sh[];
    const int M = 2 * N;
    float4* seg    = reinterpret_cast<float4*>(sh);               // M+1
    float2* sp     = reinterpret_cast<float2*>(seg + (M + 1));    // N
    float2* raw    = sp + N;                                      // N
    float*  slab   = reinterpret_cast<float*>(raw + N);           // N
    float*  rawlab = slab + N;                                    // N
    float*  ebp    = rawlab + N;                                  // M+1 (INF pad)
    unsigned short* lut = reinterpret_cast<unsigned short*>(ebp + (M + 1));

    const int b = blockIdx.y;
    const float* tg = targets + (size_t)b * N * 3;

    if (threadIdx.x < N) {
        int i = threadIdx.x;
        raw[i]    = make_float2(tg[i * 3 + 0] * 256.0f, tg[i * 3 + 1] * 256.0f);
        rawlab[i] = tg[i * 3 + 2];
    }
    __syncthreads();
    if (threadIdx.x < N) {                          // stable width rank-sort
        int i = threadIdx.x;
        float2 ti = raw[i];
        float  wi = ti.y - ti.x;
        int rank = 0;
        for (int j = 0; j < N; j++) {
            float2 tj = raw[j];
            float  wj = tj.y - tj.x;
            rank += (wj < wi) || (wj == wi && j < i);
        }
        sp[rank]   = ti;
        slab[rank] = rawlab[i];
    }
    if (threadIdx.x < M) {                          // stable endpoint rank-sort
        int i = threadIdx.x;
        float vi = (i < N) ? raw[i].x : raw[i - N].y;
        int rank = 0;
        for (int j = 0; j < M; j++) {
            float vj = (j < N) ? raw[j].x : raw[j - N].y;
            rank += (vj < vi) || (vj == vi && j < i);
        }
        ebp[rank] = vi;
    }
    if (threadIdx.x == M) ebp[M] = CUDART_INF_F;
    __syncthreads();
    for (int s = threadIdx.x; s <= M; s += blockDim.x) {   // segment table
        float rep;
        if (s == 0)      rep = ebp[0] - 1.0f;
        else if (s == M) rep = ebp[M - 1] + 1.0f;
        else             rep = 0.5f * (ebp[s - 1] + ebp[s]);
        float t0 = 0.f, t1 = 0.f, lb = 0.f;
        for (int n = 0; n < N; n++) {
            float2 t = sp[n];
            if (rep >= t.x && rep <= t.y) { t0 = t.x; t1 = t.y; lb = slab[n]; break; }
        }
        seg[s] = make_float4(t0, t1, lb, ebp[s]);
    }
    for (int bin = threadIdx.x; bin < LUTSIZE; bin += blockDim.x) {
        float edge = (float)bin * (256.0f / LUTSIZE);
        int s = 0;
        #pragma unroll
        for (int step = 64; step >= 1; step >>= 1) {
            int ns = s + step;
            if (ns <= M && ebp[ns - 1] < edge) s = ns;
        }
        lut[bin] = (unsigned short)s;
    }
    __syncthreads();

    Accum A = {0.f, 0.f, 0.f, 0.f, 0.f, 0.f, 0.f};
    const int Kh = K >> 1;                          // pairs
    const size_t baseh = (size_t)b * (size_t)Kh;

    const float4* loc4  = reinterpret_cast<const float4*>(loc)     + baseh;
    const float4* cd4   = reinterpret_cast<const float4*>(conf_d)  + baseh;
    const float4* pld4  = reinterpret_cast<const float4*>(ploc)    + baseh;
    const float4* pcd4  = reinterpret_cast<const float4*>(pconf_d) + baseh;
    const float2* ctr2  = reinterpret_cast<const float2*>(center)  + baseh;
    const float2* pri2  = reinterpret_cast<const float2*>(priors);

    const int stride = gridDim.x * blockDim.x;

    // ---- software-pipelined main loop (register double buffer) ----
    PairBuf bufA, bufB;
    int p = blockIdx.x * blockDim.x + threadIdx.x;
    bool valid = (p < Kh);
    if (valid) load_pair(p, pri2, ctr2, loc4, pld4, cd4, pcd4, bufA);
    while (valid) {
        int  pn = p + stride;
        bool vn = (pn < Kh);
        if (vn) load_pair(pn, pri2, ctr2, loc4, pld4, cd4, pcd4, bufB);
        process_pair(bufA, seg, lut, A);
        p = pn; valid = vn;
        if (!valid) break;
        pn = p + stride;
        vn = (pn < Kh);
        if (vn) load_pair(pn, pri2, ctr2, loc4, pld4, cd4, pcd4, bufA);
        process_pair(bufB, seg, lut, A);
        p = pn; valid = vn;
    }

    // odd-K tail (not hit for K=200000; kept for generality)
    if ((K & 1) && blockIdx.x == 0 && threadIdx.x == 0) {
        const size_t base = (size_t)b * (size_t)K;
        int k = K - 1;
        float c = priors[k] * 256.0f;
        int s = lut[(int)(priors[k] * (float)LUTSIZE)];
        float4 sgk = seg[s];
        while (sgk.w < c) { s++; sgk = seg[s]; }
        float2 pre = reinterpret_cast<const float2*>(loc)[base + k];
        float2 pld = reinterpret_cast<const float2*>(ploc)[base + k];
        float2 cd  = reinterpret_cast<const float2*>(conf_d)[base + k];
        float2 pcd = reinterpret_cast<const float2*>(pconf_d)[base + k];
        epilogue_elem(c, sgk, pre.x, pre.y, cd.x, cd.y,
                      pld.x, pld.y, pcd.x, pcd.y, center[base + k], A);
    }

    // warp reduction
    #pragma unroll
    for (int off = 16; off; off >>= 1) {
        A.a0 += __shfl_down_sync(0xffffffffu, A.a0, off);
        A.a1 += __shfl_down_sync(0xffffffffu, A.a1, off);
        A.a2 += __shfl_down_sync(0xffffffffu, A.a2, off);
        A.a3 += __shfl_down_sync(0xffffffffu, A.a3, off);
        A.a4 += __shfl_down_sync(0xffffffffu, A.a4, off);
        A.a5 += __shfl_down_sync(0xffffffffu, A.a5, off);
        A.a6 += __shfl_down_sync(0xffffffffu, A.a6, off);
    }
    __shared__ float red[8][8];
    int w  = threadIdx.x >> 5;
    int ln = threadIdx.x & 31;
    if (ln == 0) {
        red[w][0] = A.a0; red[w][1] = A.a1; red[w][2] = A.a2; red[w][3] = A.a3;
        red[w][4] = A.a4; red[w][5] = A.a5; red[w][6] = A.a6;
    }
    __syncthreads();
    const int blk = blockIdx.y * gridDim.x + blockIdx.x;
    if (threadIdx.x < 7) {
        float v = 0.0f;
        #pragma unroll
        for (int i = 0; i < 8; i++) v += red[i][threadIdx.x];
        g_part[blk * 8 + threadIdx.x] = v;   // deterministic per-block slot
    }
    __syncthreads();

    // ---- last-block finalize (deterministic fixed-order sum) ----
    __shared__ unsigned int s_ticket;
    if (threadIdx.x == 0) {
        __threadfence();
        s_ticket = atomicAdd(&g_count, 1u);
    }
    __syncthreads();
    if (s_ticket == (unsigned)(nblk - 1)) {
        __threadfence();
        __shared__ float tot[7];
        if (w < 7) {
            float v = 0.0f;
            for (int i = ln; i < nblk; i += 32) v += g_part[i * 8 + w];
            #pragma unroll
            for (int off = 16; off; off >>= 1) v += __shfl_down_sync(0xffffffffu, v, off);
            if (ln == 0) tot[w] = v;
        }
        __syncthreads();
        if (threadIdx.x == 0) {
            g_count = 0;                       // self-reset for graph replay
            float np = fmaxf(tot[5], 1.0f);
            float pn = fmaxf(tot[6], 1.0f);
            if (out_size > 0) out[0] = tot[0] / np;   // loss_l / Np
            if (out_size > 1) out[1] = tot[1] / np;   // loss_c / Np
            if (out_size > 2) out[2] = tot[2] / pn;   // loss_prop_l / PN
            if (out_size > 3) out[3] = tot[3] / pn;   // loss_prop_c / PN
            if (out_size > 4) out[4] = tot[4] / np;   // loss_ct / Np
        }
    }
}

extern "C" void kernel_launch(void* const* d_in, const int* in_sizes, int n_in,
                              void* d_out, int out_size)
{
    const float* loc     = (const float*)d_in[0];
    const float* conf    = (const float*)d_in[1];
    const float* ploc    = (const float*)d_in[2];
    const float* pconf   = (const float*)d_in[3];
    const float* center  = (const float*)d_in[4];
    const float* priors  = (const float*)d_in[5];
    const float* targets = (const float*)d_in[6];

    int K = in_sizes[5];                 // priors: (K,1)
    int B = in_sizes[4] / K;             // center: (B,K,1)
    int N = in_sizes[6] / (B * 3);       // targets: (B,N,3)
    int M = 2 * N;

    // Single wave at 3 blocks/SM: 3 * 148 = 444 slots.
    int gx = 444 / (B > 0 ? B : 1);
    if (gx < 1) gx = 1;
    while ((long)gx * B > MAXPART && gx > 1) gx /= 2;
    int nblk = gx * B;

    dim3 grid(gx, B);
    size_t shmem = (size_t)(M + 1) * 16        // seg float4
                 + (size_t)N * 8 * 2           // sp + raw float2
                 + (size_t)N * 4 * 2           // slab + rawlab
                 + (size_t)(M + 1) * 4         // ebp (+sentinel)
                 + (size_t)LUTSIZE * 2;        // u16 lut
    msl_main<<<grid, 256, shmem>>>(loc, conf, ploc, pconf, center, priors,
                                   targets, K, N, nblk, (float*)d_out, out_size);
}

// round 16
// speedup vs baseline: 1.0667x; 1.0533x over previous
#include <cuda_runtime.h>
#include <math_constants.h>

// ---------------------------------------------------------------------------
// MultiSegmentLoss fused kernel — R9 structure (single launch, single wave at
// 2 blocks/SM, x4 elements/thread, register double-buffered loads, QUAD-phased
// batched match) + chain-shortening math:
//   GIoU==IoU identity (plain divide), focal via softplus/sigmoid algebra
//   (parallel RCP/LG2 chains, eps dropped), a2 via cl-reuse.
// ---------------------------------------------------------------------------

#define MAXPART 8192
#define LUTSIZE 4096                    // bins over [0,256) -> width 1/16

__device__ float        g_part[MAXPART * 8];
__device__ unsigned int g_count = 0;

struct Accum { float a0, a1, a2, a3, a4, a5, a6; };

__device__ __forceinline__ void epilogue_elem(
    float c256, const float4 sg, float pl, float pr, float cdx, float cdy,
    float pldx, float pldy, float pcdx, float pcdy, float lg, Accum& A)
{
    const float EPS = 1.1920929e-7f;   // jnp.finfo(float32).eps

    const bool pos = (sg.z > 0.0f);
    float ltl = c256 - sg.x;
    float ltr = sg.y - c256;

    float inter = fminf(pl, ltl) + fminf(pr, ltr);
    float uni   = pl + pr + ltl + ltr - inter;   // == max+max >= pl+pr >= 2
    const bool ppos = pos && (inter >= 0.5f * uni);   // iou >= 0.5
    float posf = pos  ? 1.0f : 0.0f;
    float ppf  = ppos ? 1.0f : 0.0f;

    // 1-D identity: enclosing interval == union, so giou == iou (plain divide,
    // shortest chain; uni > 0 always since uni = max+max >= pl+pr >= 2).
    A.a0 += (1.0f - __fdividef(inter, uni)) * posf;

    float hw  = 0.5f * (pl + pr);
    float rhw = __fdividef(1.0f, hw);            // independent MUFU chain
    float cl0 = hw * pldx + pl;
    float cl1 = hw * pldy + pr;

    // prop-loc L1: pldx-(ltl-pl)/hw == (cl0-ltl)*rhw
    A.a2 += (fabsf(cl0 - ltl) + fabsf(cl1 - ltr)) * rhw * ppf;

    // centerness BCE vs clipped iou of refined location
    float in2  = fminf(cl0, ltl) + fminf(cl1, ltr);
    float un2  = cl0 + cl1 + ltl + ltr - in2;
    float iou2 = fmaxf(__fdividef(in2, fmaxf(un2, EPS)), 0.0f);
    float bce  = fmaxf(lg, 0.0f) - lg * iou2 + __logf(1.0f + __expf(-fabsf(lg)));
    A.a4 += bce * posf;

    // focal(conf): pt = sigmoid(-d), so log(pt) = -softplus(d), 1-pt = sigmoid(d).
    // term = (1-pt)^2 * alpha * softplus(d); RCP and LG2 chains share (1+e)
    // and run in parallel. (+1e-6 on pt dropped: |d| <~ 10 sigma so pt >= ~5e-5,
    // local effect <= 2% on ~1e-11 of elements — far below 1e-3 tolerance.)
    {
        float dd = cdx - cdy;
        float d  = pos ? dd : -dd;
        float e  = __expf(d);
        float q  = 1.0f + e;
        float t  = __fdividef(1.0f, q);     // parallel with __logf(q)
        float splus = __logf(q);            // softplus(d)
        float om = e * t;                   // 1 - pt
        float al = pos ? 0.75f : 0.25f;
        A.a1 += om * om * al * splus;
    }
    // focal(prop_conf)
    {
        float dd = pcdx - pcdy;
        float d  = ppos ? dd : -dd;
        float e  = __expf(d);
        float q  = 1.0f + e;
        float t  = __fdividef(1.0f, q);
        float splus = __logf(q);
        float om = e * t;
        float al = ppos ? 0.75f : 0.25f;
        A.a3 += om * om * al * splus;
    }
    A.a5 += posf;
    A.a6 += ppf;
}

struct QuadBuf { float4 v[10]; };   // pc, lg, pre0, pre1, pld0, pld1, cd0, cd1, pcd0, pcd1

__device__ __forceinline__ void load_quad(
    int q,
    const float4* __restrict__ pri4, const float4* __restrict__ ctr4,
    const float4* __restrict__ loc4, const float4* __restrict__ pld4,
    const float4* __restrict__ cd4,  const float4* __restrict__ pcd4,
    QuadBuf& B)
{
    B.v[0] = pri4[q];                    // priors reused across batches -> cache
    B.v[1] = __ldcs(ctr4 + q);
    B.v[2] = __ldcs(loc4 + 2 * q);
    B.v[3] = __ldcs(loc4 + 2 * q + 1);
    B.v[4] = __ldcs(pld4 + 2 * q);
    B.v[5] = __ldcs(pld4 + 2 * q + 1);
    B.v[6] = __ldcs(cd4  + 2 * q);
    B.v[7] = __ldcs(cd4  + 2 * q + 1);
    B.v[8] = __ldcs(pcd4 + 2 * q);
    B.v[9] = __ldcs(pcd4 + 2 * q + 1);
}

__device__ __forceinline__ void process_quad(
    const QuadBuf& B, const float4* __restrict__ seg,
    const unsigned short* __restrict__ lut, Accum& A)
{
    // ---- phase 1: batched matches (4 overlapping LDS chains) ----
    float c[4] = { B.v[0].x * 256.0f, B.v[0].y * 256.0f,
                   B.v[0].z * 256.0f, B.v[0].w * 256.0f };
    int si[4];
    #pragma unroll
    for (int i = 0; i < 4; i++)
        si[i] = lut[(int)(c[i] * (LUTSIZE / 256.0f))];
    float4 sg[4];
    #pragma unroll
    for (int i = 0; i < 4; i++)
        sg[i] = seg[si[i]];
    #pragma unroll
    for (int i = 0; i < 4; i++)
        while (sg[i].w < c[i]) { si[i]++; sg[i] = seg[si[i]]; }   // rare, bounded

    // ---- phase 2: 4 independent epilogue chains, operands all ready ----
    epilogue_elem(c[0], sg[0], B.v[2].x, B.v[2].y, B.v[6].x, B.v[6].y,
                  B.v[4].x, B.v[4].y, B.v[8].x, B.v[8].y, B.v[1].x, A);
    epilogue_elem(c[1], sg[1], B.v[2].z, B.v[2].w, B.v[6].z, B.v[6].w,
                  B.v[4].z, B.v[4].w, B.v[8].z, B.v[8].w, B.v[1].y, A);
    epilogue_elem(c[2], sg[2], B.v[3].x, B.v[3].y, B.v[7].x, B.v[7].y,
                  B.v[5].x, B.v[5].y, B.v[9].x, B.v[9].y, B.v[1].z, A);
    epilogue_elem(c[3], sg[3], B.v[3].z, B.v[3].w, B.v[7].z, B.v[7].w,
                  B.v[5].z, B.v[5].w, B.v[9].z, B.v[9].w, B.v[1].w, A);
}

__global__ __launch_bounds__(256, 2) void msl_main(
    const float* __restrict__ loc,
    const float* __restrict__ conf_d,
    const float* __restrict__ ploc,
    const float* __restrict__ pconf_d,
    const float* __restrict__ center,
    const float* __restrict__ priors,
    const float* __restrict__ targets,
    int K, int N, int nblk,
    float* __restrict__ out, int out_size)
{
    extern __shared__ float sh[];
    const int M = 2 * N;
    float4* seg    = reinterpret_cast<float4*>(sh);               // M+1
    float2* sp     = reinterpret_cast<float2*>(seg + (M + 1));    // N
    float2* raw    = sp + N;                                      // N
    float*  slab   = reinterpret_cast<float*>(raw + N);           // N
    float*  rawlab = slab + N;                                    // N
    float*  ebp    = rawlab + N;                                  // M+1 (INF pad)
    unsigned short* lut = reinterpret_cast<unsigned short*>(ebp + (M + 1));

    const int b = blockIdx.y;
    const float* tg = targets + (size_t)b * N * 3;

    if (threadIdx.x < N) {
        int i = threadIdx.x;
        raw[i]    = make_float2(tg[i * 3 + 0] * 256.0f, tg[i * 3 + 1] * 256.0f);
        rawlab[i] = tg[i * 3 + 2];
    }
    __syncthreads();
    if (threadIdx.x < N) {                          // stable width rank-sort
        int i = threadIdx.x;
        float2 ti = raw[i];
        float  wi = ti.y - ti.x;
        int rank = 0;
        for (int j = 0; j < N; j++) {
            float2 tj = raw[j];
            float  wj = tj.y - tj.x;
            rank += (wj < wi) || (wj == wi && j < i);
        }
        sp[rank]   = ti;
        slab[rank] = rawlab[i];
    }
    if (threadIdx.x < M) {                          // stable endpoint rank-sort
        int i = threadIdx.x;
        float vi = (i < N) ? raw[i].x : raw[i - N].y;
        int rank = 0;
        for (int j = 0; j < M; j++) {
            float vj = (j < N) ? raw[j].x : raw[j - N].y;
            rank += (vj < vi) || (vj == vi && j < i);
        }
        ebp[rank] = vi;
    }
    if (threadIdx.x == M) ebp[M] = CUDART_INF_F;
    __syncthreads();
    for (int s = threadIdx.x; s <= M; s += blockDim.x) {   // segment table
        float rep;
        if (s == 0)      rep = ebp[0] - 1.0f;
        else if (s == M) rep = ebp[M - 1] + 1.0f;
        else             rep = 0.5f * (ebp[s - 1] + ebp[s]);
        float t0 = 0.f, t1 = 0.f, lb = 0.f;
        for (int n = 0; n < N; n++) {
            float2 t = sp[n];
            if (rep >= t.x && rep <= t.y) { t0 = t.x; t1 = t.y; lb = slab[n]; break; }
        }
        seg[s] = make_float4(t0, t1, lb, ebp[s]);
    }
    for (int bin = threadIdx.x; bin < LUTSIZE; bin += blockDim.x) {
        float edge = (float)bin * (256.0f / LUTSIZE);
        int s = 0;
        #pragma unroll
        for (int step = 64; step >= 1; step >>= 1) {
            int ns = s + step;
            if (ns <= M && ebp[ns - 1] < edge) s = ns;
        }
        lut[bin] = (unsigned short)s;
    }
    __syncthreads();

    Accum A = {0.f, 0.f, 0.f, 0.f, 0.f, 0.f, 0.f};
    const int Kq = K >> 2;                          // quads
    const size_t baseq = (size_t)b * (size_t)Kq;

    const float4* loc4  = reinterpret_cast<const float4*>(loc)     + 2 * baseq;
    const float4* cd4   = reinterpret_cast<const float4*>(conf_d)  + 2 * baseq;
    const float4* pld4  = reinterpret_cast<const float4*>(ploc)    + 2 * baseq;
    const float4* pcd4  = reinterpret_cast<const float4*>(pconf_d) + 2 * baseq;
    const float4* ctr4  = reinterpret_cast<const float4*>(center)  + baseq;
    const float4* pri4  = reinterpret_cast<const float4*>(priors);

    const int stride = gridDim.x * blockDim.x;

    // ---- software-pipelined main loop (register double buffer) ----
    QuadBuf bufA, bufB;
    int p = blockIdx.x * blockDim.x + threadIdx.x;
    bool valid = (p < Kq);
    if (valid) load_quad(p, pri4, ctr4, loc4, pld4, cd4, pcd4, bufA);
    while (valid) {
        int  pn = p + stride;
        bool vn = (pn < Kq);
        if (vn) load_quad(pn, pri4, ctr4, loc4, pld4, cd4, pcd4, bufB);
        process_quad(bufA, seg, lut, A);
        p = pn; valid = vn;
        if (!valid) break;
        pn = p + stride;
        vn = (pn < Kq);
        if (vn) load_quad(pn, pri4, ctr4, loc4, pld4, cd4, pcd4, bufA);
        process_quad(bufB, seg, lut, A);
        p = pn; valid = vn;
    }

    // K % 4 tail (not hit for K=200000; kept for generality)
    if ((K & 3) && blockIdx.x == 0 && threadIdx.x == 0) {
        const size_t base = (size_t)b * (size_t)K;
        for (int k = Kq * 4; k < K; k++) {
            float c = priors[k] * 256.0f;
            int s = lut[(int)(c * (LUTSIZE / 256.0f))];
            float4 sgk = seg[s];
            while (sgk.w < c) { s++; sgk = seg[s]; }
            float2 pre = reinterpret_cast<const float2*>(loc)[base + k];
            float2 pld = reinterpret_cast<const float2*>(ploc)[base + k];
            float2 cd  = reinterpret_cast<const float2*>(conf_d)[base + k];
            float2 pcd = reinterpret_cast<const float2*>(pconf_d)[base + k];
            epilogue_elem(c, sgk, pre.x, pre.y, cd.x, cd.y,
                          pld.x, pld.y, pcd.x, pcd.y, center[base + k], A);
        }
    }

    // warp reduction
    #pragma unroll
    for (int off = 16; off; off >>= 1) {
        A.a0 += __shfl_down_sync(0xffffffffu, A.a0, off);
        A.a1 += __shfl_down_sync(0xffffffffu, A.a1, off);
        A.a2 += __shfl_down_sync(0xffffffffu, A.a2, off);
        A.a3 += __shfl_down_sync(0xffffffffu, A.a3, off);
        A.a4 += __shfl_down_sync(0xffffffffu, A.a4, off);
        A.a5 += __shfl_down_sync(0xffffffffu, A.a5, off);
        A.a6 += __shfl_down_sync(0xffffffffu, A.a6, off);
    }
    __shared__ float red[8][8];
    int w  = threadIdx.x >> 5;
    int ln = threadIdx.x & 31;
    if (ln == 0) {
        red[w][0] = A.a0; red[w][1] = A.a1; red[w][2] = A.a2; red[w][3] = A.a3;
        red[w][4] = A.a4; red[w][5] = A.a5; red[w][6] = A.a6;
    }
    __syncthreads();
    const int blk = blockIdx.y * gridDim.x + blockIdx.x;
    if (threadIdx.x < 7) {
        float v = 0.0f;
        #pragma unroll
        for (int i = 0; i < 8; i++) v += red[i][threadIdx.x];
        g_part[blk * 8 + threadIdx.x] = v;   // deterministic per-block slot
    }
    __syncthreads();

    // ---- last-block finalize (deterministic fixed-order sum) ----
    __shared__ unsigned int s_ticket;
    if (threadIdx.x == 0) {
        __threadfence();
        s_ticket = atomicAdd(&g_count, 1u);
    }
    __syncthreads();
    if (s_ticket == (unsigned)(nblk - 1)) {
        __threadfence();
        __shared__ float tot[7];
        if (w < 7) {
            float v = 0.0f;
            for (int i = ln; i < nblk; i += 32) v += g_part[i * 8 + w];
            #pragma unroll
            for (int off = 16; off; off >>= 1) v += __shfl_down_sync(0xffffffffu, v, off);
            if (ln == 0) tot[w] = v;
        }
        __syncthreads();
        if (threadIdx.x == 0) {
            g_count = 0;                       // self-reset for graph replay
            float np = fmaxf(tot[5], 1.0f);
            float pn = fmaxf(tot[6], 1.0f);
            if (out_size > 0) out[0] = tot[0] / np;   // loss_l / Np
            if (out_size > 1) out[1] = tot[1] / np;   // loss_c / Np
            if (out_size > 2) out[2] = tot[2] / pn;   // loss_prop_l / PN
            if (out_size > 3) out[3] = tot[3] / pn;   // loss_prop_c / PN
            if (out_size > 4) out[4] = tot[4] / np;   // loss_ct / Np
        }
    }
}

extern "C" void kernel_launch(void* const* d_in, const int* in_sizes, int n_in,
                              void* d_out, int out_size)
{
    const float* loc     = (const float*)d_in[0];
    const float* conf    = (const float*)d_in[1];
    const float* ploc    = (const float*)d_in[2];
    const float* pconf   = (const float*)d_in[3];
    const float* center  = (const float*)d_in[4];
    const float* priors  = (const float*)d_in[5];
    const float* targets = (const float*)d_in[6];

    int K = in_sizes[5];                 // priors: (K,1)
    int B = in_sizes[4] / K;             // center: (B,K,1)
    int N = in_sizes[6] / (B * 3);       // targets: (B,N,3)
    int M = 2 * N;

    // Single wave at 2 blocks/SM: 2 * 148 = 296 slots.
    int gx = 296 / (B > 0 ? B : 1);
    if (gx < 1) gx = 1;
    while ((long)gx * B > MAXPART && gx > 1) gx /= 2;
    int nblk = gx * B;

    dim3 grid(gx, B);
    size_t shmem = (size_t)(M + 1) * 16        // seg float4
                 + (size_t)N * 8 * 2           // sp + raw float2
                 + (size_t)N * 4 * 2           // slab + rawlab
                 + (size_t)(M + 1) * 4         // ebp (+sentinel)
                 + (size_t)LUTSIZE * 2;        // u16 lut
    msl_main<<<grid, 256, shmem>>>(loc, conf, ploc, pconf, center, priors,
                                   targets, K, N, nblk, (float*)d_out, out_size);
}